// round 13
// baseline (speedup 1.0000x reference)
#include <cuda_runtime.h>
#include <cstdint>

#define B_      16
#define C_      3
#define HW_     (512 * 512)
#define HW4_    (HW_ / 4)            /* 65536 float4 vectors per image */
#define NCLS    64
#define NSEG    (B_ * NCLS)
#define STRIDE  32                   /* u64 elems -> 256 B bin stride */
#define NBLKX   27                   /* blocks per image; 27*16=432 <= 444 slots */
#define NBLK    (NBLKX * B_)
#define THREADS 128
#define NWARP   4

#define HIST_BYTES   (NWARP * NCLS * 32 * 4)      /* 32768 */
#define NSTREAM      7                            /* in0,in1,in2,tg0,tg1,tg2,mask */
#define STREAM_PITCH (THREADS * 16)               /* 2048 B per stream */
#define STAGE_BYTES  (NSTREAM * STREAM_PITCH)     /* 14336 */
#define SMEM_TOTAL   (HIST_BYTES + 2 * STAGE_BYTES) /* 61440 -> 3 blocks/SM */

__device__ unsigned long long d_bins[NSEG * STRIDE];
__device__ unsigned int       d_ticket;

// global packed u64: count [44:64), sum * 2^20 in [0:44)
#define GSCALE  1048576.0f
#define GINV    (1.0f / 1048576.0f)
#define GMASK   ((1ull << 44) - 1ull)
// shared packed u32 per lane-private slot (<=91 px/slot):
//   count [25:32) (max 127), sum * 2^12 in [0:25)
#define LSCALE  4096.0f
#define LCNT    (1u << 25)
#define LMASK   ((1u << 25) - 1u)
#define L2G     (GSCALE / LSCALE)    /* 256 */

// cp.async 16B with an L2 evict_last cache policy: input lines get pinned-ish
// residency in the 126MB L2 across graph replays (116MB working set fits).
__device__ __forceinline__ void cp16_el(uint32_t dst_smem, const void* src,
                                        unsigned long long pol) {
    asm volatile("cp.async.cg.shared.global.L2::cache_hint [%0], [%1], 16, %2;"
                 :: "r"(dst_smem), "l"(src), "l"(pol) : "memory");
}
__device__ __forceinline__ void cp_commit() {
    asm volatile("cp.async.commit_group;" ::: "memory");
}
template <int N>
__device__ __forceinline__ void cp_wait() {
    asm volatile("cp.async.wait_group %0;" :: "n"(N) : "memory");
}

__global__ void __launch_bounds__(THREADS)
fused_kernel(const float* __restrict__ inp,
             const float* __restrict__ tgt,
             const int*   __restrict__ msk,
             float*       __restrict__ out)
{
    extern __shared__ char smem_raw[];
    uint32_t* hist    = (uint32_t*)smem_raw;              // [NWARP][NCLS][32]
    char*     stage_g = smem_raw + HIST_BYTES;
    const uint32_t stage_s =
        (uint32_t)__cvta_generic_to_shared(smem_raw) + HIST_BYTES;

    __shared__ float    s_sum[2][NCLS];
    __shared__ uint32_t s_cnt[2][NCLS];
    __shared__ float    rtot[4], rws[4], rmx[4];
    __shared__ unsigned int s_ticket;

    const int t    = threadIdx.x;
    const int wid  = t >> 5;
    const int lane = t & 31;
    const int b    = blockIdx.y;

    // L2 evict_last policy (fraction 1.0) for all input traffic
    unsigned long long pol;
    asm volatile("createpolicy.fractional.L2::evict_last.b64 %0, 1.0;" : "=l"(pol));

    const float4* ip = (const float4*)(inp + (size_t)b * C_ * HW_);
    const float4* tp = (const float4*)(tgt + (size_t)b * C_ * HW_);
    const int4*   mp = (const int4*)  (msk + (size_t)b * HW_);

    // uneven tiling: blocks 0..6 take 2428 vectors, 7..26 take 2427
    const int start = blockIdx.x * 2427 + min(blockIdx.x, 7);
    const int len   = 2427 + (blockIdx.x < 7 ? 1 : 0);
    const int nk    = (len - t + THREADS - 1) / THREADS;  // per-thread iters (18/19)
    const int v0    = start + t;

#define CP_STAGE(kk, buf)                                                     \
    do {                                                                      \
        const uint32_t _d = stage_s + (buf) * STAGE_BYTES + t * 16;           \
        const int _v = v0 + (kk) * THREADS;                                   \
        cp16_el(_d + 0 * STREAM_PITCH, ip + _v,            pol);              \
        cp16_el(_d + 1 * STREAM_PITCH, ip + _v + HW4_,     pol);              \
        cp16_el(_d + 2 * STREAM_PITCH, ip + _v + 2 * HW4_, pol);              \
        cp16_el(_d + 3 * STREAM_PITCH, tp + _v,            pol);              \
        cp16_el(_d + 4 * STREAM_PITCH, tp + _v + HW4_,     pol);              \
        cp16_el(_d + 5 * STREAM_PITCH, tp + _v + 2 * HW4_, pol);              \
        cp16_el(_d + 6 * STREAM_PITCH, mp + _v,            pol);              \
    } while (0)

    // ---- issue stage 0 BEFORE zeroing hist (overlap first-load latency) ----
    CP_STAGE(0, 0);
    cp_commit();

    // zero this block's histograms (2048 uint4 / 128 threads)
    {
        uint4* hz = (uint4*)hist;
#pragma unroll
        for (int i = 0; i < (NWARP * NCLS * 32) / (4 * THREADS); i++)
            hz[i * THREADS + t] = make_uint4(0u, 0u, 0u, 0u);
    }
    __syncthreads();

    uint32_t* mybins = hist + wid * (NCLS * 32) + lane;

    for (int k = 0; k < nk; k++) {
        // issue stage k+1 into the other buffer
        if (k + 1 < nk) CP_STAGE(k + 1, (k + 1) & 1);
        cp_commit();               // empty group near tail is legal
        cp_wait<1>();              // stage k complete; next stage in flight

        const char* sp = stage_g + (k & 1) * STAGE_BYTES + t * 16;
        const float4 a0 = *(const float4*)(sp + 0 * STREAM_PITCH);
        const float4 a1 = *(const float4*)(sp + 1 * STREAM_PITCH);
        const float4 a2 = *(const float4*)(sp + 2 * STREAM_PITCH);
        const float4 c0 = *(const float4*)(sp + 3 * STREAM_PITCH);
        const float4 c1 = *(const float4*)(sp + 4 * STREAM_PITCH);
        const float4 c2 = *(const float4*)(sp + 5 * STREAM_PITCH);
        const int4   m  = *(const int4*)  (sp + 6 * STREAM_PITCH);

        const float w0 = fabsf(a0.x - c0.x) + fabsf(a1.x - c1.x) + fabsf(a2.x - c2.x);
        const float w1 = fabsf(a0.y - c0.y) + fabsf(a1.y - c1.y) + fabsf(a2.y - c2.y);
        const float w2 = fabsf(a0.z - c0.z) + fabsf(a1.z - c1.z) + fabsf(a2.z - c2.z);
        const float w3 = fabsf(a0.w - c0.w) + fabsf(a1.w - c1.w) + fabsf(a2.w - c2.w);

        // ---- dedup classes in registers, then INDEPENDENT parallel RMWs ----
        const uint32_t k0 = (uint32_t)m.x & (NCLS - 1);
        const uint32_t k1 = (uint32_t)m.y & (NCLS - 1);
        const uint32_t k2 = (uint32_t)m.z & (NCLS - 1);
        const uint32_t k3 = (uint32_t)m.w & (NCLS - 1);
        uint32_t u0 = LCNT + __float2uint_rn(w0 * LSCALE);
        uint32_t u1 = LCNT + __float2uint_rn(w1 * LSCALE);
        uint32_t u2 = LCNT + __float2uint_rn(w2 * LSCALE);
        uint32_t u3 = LCNT + __float2uint_rn(w3 * LSCALE);

        const bool e10 = (k1 == k0);
        const bool e20 = (k2 == k0), e21 = (k2 == k1);
        const bool e30 = (k3 == k0), e31 = (k3 == k1), e32 = (k3 == k2);
        if (e10) u0 += u1;
        if (e20) u0 += u2; else if (e21) u1 += u2;
        if (e30) u0 += u3; else if (e31) u1 += u3; else if (e32) u2 += u3;
        const bool l1 = !e10;
        const bool l2 = !(e20 | e21);
        const bool l3 = !(e30 | e31 | e32);

        uint32_t* p0 = mybins + k0 * 32;
        uint32_t* p1 = mybins + k1 * 32;
        uint32_t* p2 = mybins + k2 * 32;
        uint32_t* p3 = mybins + k3 * 32;
        const uint32_t r0 = *p0;
        const uint32_t r1 = *p1;
        const uint32_t r2 = *p2;
        const uint32_t r3 = *p3;
        *p0 = r0 + u0;
        if (l1) *p1 = r1 + u1;
        if (l2) *p2 = r2 + u2;
        if (l3) *p3 = r3 + u3;
    }
    __syncthreads();

    // ---- block flush: thread t reduces class (t&63) for warp-pair (t>>6) ----
    {
        const int c = t & 63;
        const int h = t >> 6;
        float    fs = 0.0f;
        uint32_t cc = 0u;
        const uint4* r0 = (const uint4*)(hist + (2 * h)     * (NCLS * 32) + c * 32);
        const uint4* r1 = (const uint4*)(hist + (2 * h + 1) * (NCLS * 32) + c * 32);
#pragma unroll
        for (int i = 0; i < 8; i++) {
            const int q = (i + (t & 7)) & 7;   // rotated quad -> spread banks
            const uint4 p0 = r0[q];
            const uint4 p1 = r1[q];
            cc += (p0.x >> 25) + (p0.y >> 25) + (p0.z >> 25) + (p0.w >> 25)
                + (p1.x >> 25) + (p1.y >> 25) + (p1.z >> 25) + (p1.w >> 25);
            fs += (float)(p0.x & LMASK) + (float)(p0.y & LMASK)
                + (float)(p0.z & LMASK) + (float)(p0.w & LMASK)
                + (float)(p1.x & LMASK) + (float)(p1.y & LMASK)
                + (float)(p1.z & LMASK) + (float)(p1.w & LMASK);
        }
        s_sum[h][c] = fs;
        s_cnt[h][c] = cc;
    }
    __syncthreads();

    if (t < NCLS) {
        const float    fs = s_sum[0][t] + s_sum[1][t];
        const uint32_t cc = s_cnt[0][t] + s_cnt[1][t];
        if (cc)
            atomicAdd(&d_bins[(size_t)(b * NCLS + t) * STRIDE],
                      ((unsigned long long)cc << 44) + __float2ull_rn(fs * L2G));
    }

    // ---- last-block finalize (fused) ----
    __threadfence();
    __syncthreads();
    if (t == 0) s_ticket = atomicAdd(&d_ticket, 1u);
    __syncthreads();
    if (s_ticket != NBLK - 1) return;

    __threadfence();   // acquire: all blocks' REDs visible

    float tot = 0.0f, ws = 0.0f, mx = 0.0f;
#pragma unroll
    for (int k = 0; k < NSEG / THREADS; k++) {
        const int i = k * THREADS + t;
        const unsigned long long p = d_bins[(size_t)i * STRIDE];
        d_bins[(size_t)i * STRIDE] = 0ull;          // reset for next replay
        const float        s = (float)(p & GMASK) * GINV;
        const unsigned int c = (unsigned int)(p >> 44);
        const float avg = s / fmaxf((float)c * (float)C_, 1.0f);
        tot += s;
        ws  += s * avg;
        mx   = fmaxf(mx, avg);
    }
#pragma unroll
    for (int o = 16; o > 0; o >>= 1) {
        tot += __shfl_xor_sync(0xffffffffu, tot, o);
        ws  += __shfl_xor_sync(0xffffffffu, ws,  o);
        mx   = fmaxf(mx, __shfl_xor_sync(0xffffffffu, mx, o));
    }
    if (lane == 0) { rtot[wid] = tot; rws[wid] = ws; rmx[wid] = mx; }
    __syncthreads();
    if (t == 0) {
        tot = rtot[0] + rtot[1] + rtot[2] + rtot[3];
        ws  = rws[0]  + rws[1]  + rws[2]  + rws[3];
        mx  = fmaxf(fmaxf(rmx[0], rmx[1]), fmaxf(rmx[2], rmx[3]));
        d_ticket = 0;                               // reset for next replay
        const float N = (float)B_ * (float)C_ * (float)HW_;
        const float weighted = (mx > 0.0f) ? (ws / mx) : 0.0f;   // BETA = 1
        out[0] = (tot + weighted) / N;
    }
}

extern "C" void kernel_launch(void* const* d_in, const int* in_sizes, int n_in,
                              void* d_out, int out_size)
{
    const float* inp = (const float*)d_in[0];
    const float* tgt = (const float*)d_in[1];
    const int*   msk = (const int*)  d_in[2];
    (void)in_sizes; (void)n_in; (void)out_size;

    cudaFuncSetAttribute(fused_kernel,
                         cudaFuncAttributeMaxDynamicSharedMemorySize, SMEM_TOTAL);
    fused_kernel<<<dim3(NBLKX, B_), THREADS, SMEM_TOTAL>>>(inp, tgt, msk,
                                                           (float*)d_out);
}

// round 14
// speedup vs baseline: 1.0066x; 1.0066x over previous
#include <cuda_runtime.h>
#include <cstdint>

#define B_      16
#define C_      3
#define HW_     (512 * 512)
#define HW4_    (HW_ / 4)            /* 65536 float4 vectors per image */
#define NCLS    64
#define NSEG    (B_ * NCLS)
#define STRIDE  32                   /* u64 elems -> 256 B bin stride */
#define NBLKX   27                   /* blocks per image; 27*16=432 <= 444 slots */
#define NBLK    (NBLKX * B_)
#define THREADS 128
#define NWARP   4
#define NSTAGE  3

#define HIST_BYTES   (NWARP * NCLS * 32 * 4)      /* 32768 */
#define NSTREAM      6                            /* in0,in1,in2,tg0,tg1,tg2 via cp */
#define STREAM_PITCH (THREADS * 16)               /* 2048 B per stream */
#define STAGE_BYTES  (NSTREAM * STREAM_PITCH)     /* 12288 */
#define SMEM_TOTAL   (HIST_BYTES + NSTAGE * STAGE_BYTES)  /* 69632 -> 3 blocks/SM */

__device__ unsigned long long d_bins[NSEG * STRIDE];
__device__ unsigned int       d_ticket;

// global packed u64: count [44:64), sum * 2^20 in [0:44)
#define GSCALE  1048576.0f
#define GINV    (1.0f / 1048576.0f)
#define GMASK   ((1ull << 44) - 1ull)
// shared packed u32 per lane-private slot (<=91 px/slot):
//   count [25:32) (max 127), sum * 2^12 in [0:25)
#define LSCALE  4096.0f
#define LCNT    (1u << 25)
#define LMASK   ((1u << 25) - 1u)
#define L2G     (GSCALE / LSCALE)    /* 256 */

__device__ __forceinline__ void cp16(uint32_t dst_smem, const void* src) {
    asm volatile("cp.async.cg.shared.global [%0], [%1], 16;"
                 :: "r"(dst_smem), "l"(src) : "memory");
}
__device__ __forceinline__ void cp_commit() {
    asm volatile("cp.async.commit_group;" ::: "memory");
}
template <int N>
__device__ __forceinline__ void cp_wait() {
    asm volatile("cp.async.wait_group %0;" :: "n"(N) : "memory");
}

__global__ void __launch_bounds__(THREADS)
fused_kernel(const float* __restrict__ inp,
             const float* __restrict__ tgt,
             const int*   __restrict__ msk,
             float*       __restrict__ out)
{
    extern __shared__ char smem_raw[];
    uint32_t* hist    = (uint32_t*)smem_raw;              // [NWARP][NCLS][32]
    char*     stage_g = smem_raw + HIST_BYTES;
    const uint32_t stage_s =
        (uint32_t)__cvta_generic_to_shared(smem_raw) + HIST_BYTES;

    __shared__ float    s_sum[2][NCLS];
    __shared__ uint32_t s_cnt[2][NCLS];
    __shared__ float    rtot[4], rws[4], rmx[4];
    __shared__ unsigned int s_ticket;

    const int t    = threadIdx.x;
    const int wid  = t >> 5;
    const int lane = t & 31;
    const int b    = blockIdx.y;

    const float4* ip = (const float4*)(inp + (size_t)b * C_ * HW_);
    const float4* tp = (const float4*)(tgt + (size_t)b * C_ * HW_);
    const int4*   mp = (const int4*)  (msk + (size_t)b * HW_);

    // uneven tiling: blocks 0..6 take 2428 vectors, 7..26 take 2427
    const int start = blockIdx.x * 2427 + min(blockIdx.x, 7);
    const int len   = 2427 + (blockIdx.x < 7 ? 1 : 0);
    const int nk    = (len - t + THREADS - 1) / THREADS;  // per-thread iters (18/19)
    const int v0    = start + t;

#define CP_STAGE(kk)                                                          \
    do {                                                                      \
        const uint32_t _d = stage_s + ((kk) % NSTAGE) * STAGE_BYTES + t * 16; \
        const int _v = v0 + (kk) * THREADS;                                   \
        cp16(_d + 0 * STREAM_PITCH, ip + _v);                                 \
        cp16(_d + 1 * STREAM_PITCH, ip + _v + HW4_);                          \
        cp16(_d + 2 * STREAM_PITCH, ip + _v + 2 * HW4_);                      \
        cp16(_d + 3 * STREAM_PITCH, tp + _v);                                 \
        cp16(_d + 4 * STREAM_PITCH, tp + _v + HW4_);                          \
        cp16(_d + 5 * STREAM_PITCH, tp + _v + 2 * HW4_);                      \
    } while (0)

    // ---- prologue: stages 0,1 in flight; mask iter-0 via LDG ----
    CP_STAGE(0); cp_commit();
    CP_STAGE(1); cp_commit();                 // nk >= 18 always
    int4 m_cur = __ldcs(mp + v0);

    // zero this block's histograms (2048 uint4 / 128 threads)
    {
        uint4* hz = (uint4*)hist;
#pragma unroll
        for (int i = 0; i < (NWARP * NCLS * 32) / (4 * THREADS); i++)
            hz[i * THREADS + t] = make_uint4(0u, 0u, 0u, 0u);
    }
    __syncthreads();

    uint32_t* mybins = hist + wid * (NCLS * 32) + lane;

    for (int k = 0; k < nk; k++) {
        // keep cp pipeline 2 full groups deep; mask prefetch 1 iter ahead
        if (k + 2 < nk) CP_STAGE(k + 2);
        cp_commit();                 // empty group near tail is legal
        int4 m_nxt;
        if (k + 1 < nk) m_nxt = __ldcs(mp + v0 + (k + 1) * THREADS);
        cp_wait<2>();                // stage k ready; 2 groups stay in flight

        const char* sp = stage_g + (k % NSTAGE) * STAGE_BYTES + t * 16;
        const float4 a0 = *(const float4*)(sp + 0 * STREAM_PITCH);
        const float4 a1 = *(const float4*)(sp + 1 * STREAM_PITCH);
        const float4 a2 = *(const float4*)(sp + 2 * STREAM_PITCH);
        const float4 c0 = *(const float4*)(sp + 3 * STREAM_PITCH);
        const float4 c1 = *(const float4*)(sp + 4 * STREAM_PITCH);
        const float4 c2 = *(const float4*)(sp + 5 * STREAM_PITCH);
        const int4   m  = m_cur;

        const float w0 = fabsf(a0.x - c0.x) + fabsf(a1.x - c1.x) + fabsf(a2.x - c2.x);
        const float w1 = fabsf(a0.y - c0.y) + fabsf(a1.y - c1.y) + fabsf(a2.y - c2.y);
        const float w2 = fabsf(a0.z - c0.z) + fabsf(a1.z - c1.z) + fabsf(a2.z - c2.z);
        const float w3 = fabsf(a0.w - c0.w) + fabsf(a1.w - c1.w) + fabsf(a2.w - c2.w);

        // ---- dedup classes in registers, then INDEPENDENT parallel RMWs ----
        const uint32_t k0 = (uint32_t)m.x & (NCLS - 1);
        const uint32_t k1 = (uint32_t)m.y & (NCLS - 1);
        const uint32_t k2 = (uint32_t)m.z & (NCLS - 1);
        const uint32_t k3 = (uint32_t)m.w & (NCLS - 1);
        uint32_t u0 = LCNT + __float2uint_rn(w0 * LSCALE);
        uint32_t u1 = LCNT + __float2uint_rn(w1 * LSCALE);
        uint32_t u2 = LCNT + __float2uint_rn(w2 * LSCALE);
        uint32_t u3 = LCNT + __float2uint_rn(w3 * LSCALE);

        const bool e10 = (k1 == k0);
        const bool e20 = (k2 == k0), e21 = (k2 == k1);
        const bool e30 = (k3 == k0), e31 = (k3 == k1), e32 = (k3 == k2);
        if (e10) u0 += u1;
        if (e20) u0 += u2; else if (e21) u1 += u2;
        if (e30) u0 += u3; else if (e31) u1 += u3; else if (e32) u2 += u3;
        const bool l1 = !e10;
        const bool l2 = !(e20 | e21);
        const bool l3 = !(e30 | e31 | e32);

        uint32_t* p0 = mybins + k0 * 32;
        uint32_t* p1 = mybins + k1 * 32;
        uint32_t* p2 = mybins + k2 * 32;
        uint32_t* p3 = mybins + k3 * 32;
        const uint32_t r0 = *p0;
        const uint32_t r1 = *p1;
        const uint32_t r2 = *p2;
        const uint32_t r3 = *p3;
        *p0 = r0 + u0;
        if (l1) *p1 = r1 + u1;
        if (l2) *p2 = r2 + u2;
        if (l3) *p3 = r3 + u3;

        m_cur = m_nxt;
    }
    __syncthreads();

    // ---- block flush: thread t reduces class (t&63) for warp-pair (t>>6) ----
    {
        const int c = t & 63;
        const int h = t >> 6;
        float    fs = 0.0f;
        uint32_t cc = 0u;
        const uint4* r0 = (const uint4*)(hist + (2 * h)     * (NCLS * 32) + c * 32);
        const uint4* r1 = (const uint4*)(hist + (2 * h + 1) * (NCLS * 32) + c * 32);
#pragma unroll
        for (int i = 0; i < 8; i++) {
            const int q = (i + (t & 7)) & 7;   // rotated quad -> spread banks
            const uint4 p0 = r0[q];
            const uint4 p1 = r1[q];
            cc += (p0.x >> 25) + (p0.y >> 25) + (p0.z >> 25) + (p0.w >> 25)
                + (p1.x >> 25) + (p1.y >> 25) + (p1.z >> 25) + (p1.w >> 25);
            fs += (float)(p0.x & LMASK) + (float)(p0.y & LMASK)
                + (float)(p0.z & LMASK) + (float)(p0.w & LMASK)
                + (float)(p1.x & LMASK) + (float)(p1.y & LMASK)
                + (float)(p1.z & LMASK) + (float)(p1.w & LMASK);
        }
        s_sum[h][c] = fs;
        s_cnt[h][c] = cc;
    }
    __syncthreads();

    if (t < NCLS) {
        const float    fs = s_sum[0][t] + s_sum[1][t];
        const uint32_t cc = s_cnt[0][t] + s_cnt[1][t];
        if (cc)
            atomicAdd(&d_bins[(size_t)(b * NCLS + t) * STRIDE],
                      ((unsigned long long)cc << 44) + __float2ull_rn(fs * L2G));
    }

    // ---- last-block finalize (fused) ----
    __threadfence();
    __syncthreads();
    if (t == 0) s_ticket = atomicAdd(&d_ticket, 1u);
    __syncthreads();
    if (s_ticket != NBLK - 1) return;

    __threadfence();   // acquire: all blocks' REDs visible

    float tot = 0.0f, ws = 0.0f, mx = 0.0f;
#pragma unroll
    for (int k = 0; k < NSEG / THREADS; k++) {
        const int i = k * THREADS + t;
        const unsigned long long p = d_bins[(size_t)i * STRIDE];
        d_bins[(size_t)i * STRIDE] = 0ull;          // reset for next replay
        const float        s = (float)(p & GMASK) * GINV;
        const unsigned int c = (unsigned int)(p >> 44);
        const float avg = s / fmaxf((float)c * (float)C_, 1.0f);
        tot += s;
        ws  += s * avg;
        mx   = fmaxf(mx, avg);
    }
#pragma unroll
    for (int o = 16; o > 0; o >>= 1) {
        tot += __shfl_xor_sync(0xffffffffu, tot, o);
        ws  += __shfl_xor_sync(0xffffffffu, ws,  o);
        mx   = fmaxf(mx, __shfl_xor_sync(0xffffffffu, mx, o));
    }
    if (lane == 0) { rtot[wid] = tot; rws[wid] = ws; rmx[wid] = mx; }
    __syncthreads();
    if (t == 0) {
        tot = rtot[0] + rtot[1] + rtot[2] + rtot[3];
        ws  = rws[0]  + rws[1]  + rws[2]  + rws[3];
        mx  = fmaxf(fmaxf(rmx[0], rmx[1]), fmaxf(rmx[2], rmx[3]));
        d_ticket = 0;                               // reset for next replay
        const float N = (float)B_ * (float)C_ * (float)HW_;
        const float weighted = (mx > 0.0f) ? (ws / mx) : 0.0f;   // BETA = 1
        out[0] = (tot + weighted) / N;
    }
}

extern "C" void kernel_launch(void* const* d_in, const int* in_sizes, int n_in,
                              void* d_out, int out_size)
{
    const float* inp = (const float*)d_in[0];
    const float* tgt = (const float*)d_in[1];
    const int*   msk = (const int*)  d_in[2];
    (void)in_sizes; (void)n_in; (void)out_size;

    cudaFuncSetAttribute(fused_kernel,
                         cudaFuncAttributeMaxDynamicSharedMemorySize, SMEM_TOTAL);
    fused_kernel<<<dim3(NBLKX, B_), THREADS, SMEM_TOTAL>>>(inp, tgt, msk,
                                                           (float*)d_out);
}